// round 4
// baseline (speedup 1.0000x reference)
#include <cuda_runtime.h>
#include <cstdint>

// Problem constants:
//   B=8, H=8, L=1024, D=64, K=49
//   x:  (B,H,L,D) fp32   = d_in[0]
//   W:  (H,D,K)   fp32   = d_in[1]
//   rp: (L,L)     int32  = d_in[2]
//   out:(B,H,L,L) fp32
#define BB 8
#define HH 8
#define LL 1024
#define DD 64
#define KK 49
#define BH (BB*HH)

#define WS_STRIDE 50   // padded W row stride in smem

// ---------------------------------------------------------------------------
// Fused kernel: block (i, h) computes lt rows for bh = b*8+h (b = warp id)
// and immediately gathers/stores out[bh, i, :].
//
//   lt[b][k] = sum_d x[b,h,i,d] * W[h,d,k]        (each warp: 2 acc per lane)
//   out[bh,i,j] = lt[b][ rp[i,j] ]                (8 float4 stores per lane)
//
// grid: (L, H) = (1024, 8), block: 256 (8 warps = 8 b's)
// ---------------------------------------------------------------------------
__global__ __launch_bounds__(256) void irpe_fused_kernel(
    const float* __restrict__ x, const float* __restrict__ W,
    const int* __restrict__ rp, float* __restrict__ out)
{
    const int i   = blockIdx.x;
    const int h   = blockIdx.y;
    const int tid = threadIdx.x;
    const int w   = tid >> 5;     // warp id = b (0..7)
    const int lane = tid & 31;

    __shared__ float Ws[DD * WS_STRIDE];   // 12.8 KB
    __shared__ float xs[BB * DD];          // 2 KB
    __shared__ int   bs[LL];               // 4 KB
    __shared__ float lts[BB * KK];         // 1.57 KB

    // Stage rp row (256 int4, coalesced)
    ((int4*)bs)[tid] = ((const int4*)(rp + (size_t)i * LL))[tid];

    // Stage W[h] into stride-50 rows (L2-resident broadcast across blocks)
    {
        const float* Wh = W + (size_t)h * DD * KK;
        #pragma unroll
        for (int t = tid; t < DD * KK; t += 256) {
            const int d = t / KK;
            const int k = t - d * KK;
            Ws[d * WS_STRIDE + k] = Wh[t];
        }
    }

    // Stage x rows: 8 b's x 64 d = 128 float4 (threads 0..127)
    if (tid < BB * (DD / 4)) {
        const int b    = tid >> 4;
        const int dpos = (tid & 15) << 2;
        const int bh   = b * HH + h;
        float4 v = *(const float4*)(x + ((size_t)bh * LL + i) * DD + dpos);
        float* dst = xs + b * DD + dpos;
        dst[0] = v.x; dst[1] = v.y; dst[2] = v.z; dst[3] = v.w;
    }
    __syncthreads();

    // Compute lt row for b = w: lane covers k = lane and k = lane + 32
    {
        float acc0 = 0.0f, acc1 = 0.0f;
        const float* xrow = xs + w * DD;
        const bool has2 = (lane < KK - 32);   // lane < 17
        #pragma unroll 8
        for (int d = 0; d < DD; d++) {
            const float xv = xrow[d];                 // broadcast LDS
            const float* wd = Ws + d * WS_STRIDE;
            acc0 = fmaf(xv, wd[lane], acc0);
            acc1 = fmaf(xv, has2 ? wd[lane + 32] : 0.0f, acc1);
        }
        lts[w * KK + lane] = acc0;
        if (has2) lts[w * KK + lane + 32] = acc1;
    }
    __syncwarp();

    // Gather + streaming store: warp w owns row (bh = w*8+h, i)
    {
        const float* row = lts + w * KK;
        const int bh = w * HH + h;
        float* dst = out + (((size_t)bh * LL) + i) * LL;
        #pragma unroll
        for (int it = 0; it < 8; it++) {
            const int j4 = it * 32 + lane;
            const int4 bk = ((const int4*)bs)[j4];
            float4 v;
            v.x = row[bk.x];
            v.y = row[bk.y];
            v.z = row[bk.z];
            v.w = row[bk.w];
            __stcs((float4*)dst + j4, v);   // streaming: don't pollute L2
        }
    }
}

// ---------------------------------------------------------------------------
extern "C" void kernel_launch(void* const* d_in, const int* in_sizes, int n_in,
                              void* d_out, int out_size)
{
    const float* x  = (const float*)d_in[0];
    const float* W  = (const float*)d_in[1];
    const int*   rp = (const int*)d_in[2];
    float*       out = (float*)d_out;

    dim3 grid(LL, HH);
    irpe_fused_kernel<<<grid, 256>>>(x, W, rp, out);
}

// round 5
// speedup vs baseline: 1.3523x; 1.3523x over previous
#include <cuda_runtime.h>
#include <cstdint>

// Problem constants:
//   B=8, H=8, L=1024, D=64, K=49
//   x:  (B,H,L,D) fp32   = d_in[0]
//   W:  (H,D,K)   fp32   = d_in[1]
//   rp: (L,L)     int32  = d_in[2]
//   out:(B,H,L,L) fp32
#define BB 8
#define HH 8
#define LL 1024
#define DD 64
#define KK 49
#define BH (BB*HH)

#define WS_STRIDE 50       // padded W row stride in smem (even -> aligned pairs)
#define IPB 8              // i-rows per block (one per warp)

// ---------------------------------------------------------------------------
// Fused kernel v2.
// Block (i-group, h): 8 warps; warp w owns i = i0+w and ALL 8 b's.
//   compute: lt[b][k] in registers (b-pairs packed in fma.rn.f32x2,
//            x broadcast via shfl from registers, W: 2 LDS per d per warp)
//   gather:  STS lt -> smem once, then out[bh,i,j] = lt[b][rp[i,j]]
//            (rp read from global LDG.128, reused across 8 b in registers)
// grid: (L/8, H) = (128, 8), block: 256
// ---------------------------------------------------------------------------
__global__ __launch_bounds__(256, 4) void irpe_fused2_kernel(
    const float* __restrict__ x, const float* __restrict__ W,
    const int* __restrict__ rp, float* __restrict__ out)
{
    const int h    = blockIdx.y;
    const int i0   = blockIdx.x * IPB;
    const int tid  = threadIdx.x;
    const int w    = tid >> 5;
    const int lane = tid & 31;
    const int i    = i0 + w;

    __shared__ float Ws[DD * WS_STRIDE + 32];   // ~12.9 KB (pad: safe lane+32 reads)
    __shared__ float lts[IPB * BB * KK];        // 8*8*49 floats = 12.25 KB

    // Stage W[h] into stride-50 rows
    {
        const float* Wh = W + (size_t)h * DD * KK;
        #pragma unroll
        for (int t = tid; t < DD * KK; t += 256) {
            const int d = t / KK;
            const int k = t - d * KK;
            Ws[d * WS_STRIDE + k] = Wh[t];
        }
    }

    // Load x into registers: lane (b=lane>>2, q=lane&3) holds x[b*8+h, i, q*16..q*16+15]
    float xr[16];
    {
        const int b = lane >> 2;
        const int q = lane & 3;
        const float4* src = (const float4*)(x + ((size_t)(b * HH + h) * LL + i) * DD + q * 16);
        #pragma unroll
        for (int n = 0; n < 4; n++) {
            float4 v = src[n];
            xr[n * 4 + 0] = v.x; xr[n * 4 + 1] = v.y;
            xr[n * 4 + 2] = v.z; xr[n * 4 + 3] = v.w;
        }
    }
    __syncthreads();

    // Compute: acc[bp]   = lt[{2bp,2bp+1}][lane]      (packed f32x2)
    //          acc[4+bp] = lt[{2bp,2bp+1}][lane+32]   (valid for lane<17)
    unsigned long long acc[8];
    #pragma unroll
    for (int j = 0; j < 8; j++) acc[j] = 0ull;

    for (int q = 0; q < 4; q++) {
        #pragma unroll
        for (int d2 = 0; d2 < 16; d2++) {
            const int d = q * 16 + d2;
            const float w0 = Ws[d * WS_STRIDE + lane];
            const float w1 = Ws[d * WS_STRIDE + 32 + lane];  // garbage for lane>=17, never stored
            unsigned long long wp0, wp1;
            asm("mov.b64 %0, {%1, %1};" : "=l"(wp0) : "f"(w0));
            asm("mov.b64 %0, {%1, %1};" : "=l"(wp1) : "f"(w1));
            #pragma unroll
            for (int bp = 0; bp < 4; bp++) {
                const float x0 = __shfl_sync(0xffffffffu, xr[d2], bp * 8 + q);
                const float x1 = __shfl_sync(0xffffffffu, xr[d2], bp * 8 + 4 + q);
                unsigned long long xp;
                asm("mov.b64 %0, {%1, %2};" : "=l"(xp) : "f"(x0), "f"(x1));
                asm("fma.rn.f32x2 %0, %1, %2, %0;" : "+l"(acc[bp])     : "l"(xp), "l"(wp0));
                asm("fma.rn.f32x2 %0, %1, %2, %0;" : "+l"(acc[4 + bp]) : "l"(xp), "l"(wp1));
            }
        }
    }

    // Spill lt to smem (warp-local region)
    float* lw = lts + w * (BB * KK);
    #pragma unroll
    for (int bp = 0; bp < 4; bp++) {
        float lo, hi;
        asm("mov.b64 {%0, %1}, %2;" : "=f"(lo), "=f"(hi) : "l"(acc[bp]));
        lw[(2 * bp)     * KK + lane] = lo;
        lw[(2 * bp + 1) * KK + lane] = hi;
        if (lane < KK - 32) {
            asm("mov.b64 {%0, %1}, %2;" : "=f"(lo), "=f"(hi) : "l"(acc[4 + bp]));
            lw[(2 * bp)     * KK + 32 + lane] = lo;
            lw[(2 * bp + 1) * KK + 32 + lane] = hi;
        }
    }
    __syncwarp();

    // Gather + streaming stores
    const int4* rrow = (const int4*)(rp + (size_t)i * LL);
    #pragma unroll
    for (int it = 0; it < 8; it++) {
        const int4 bk = rrow[it * 32 + lane];      // coalesced LDG.128, used once
        #pragma unroll
        for (int b = 0; b < BB; b++) {
            const float* row = lw + b * KK;
            float4 v;
            v.x = row[bk.x];
            v.y = row[bk.y];
            v.z = row[bk.z];
            v.w = row[bk.w];
            float4* dst = (float4*)(out + (((size_t)(b * HH + h)) * LL + i) * LL);
            __stcs(dst + it * 32 + lane, v);
        }
    }
}

// ---------------------------------------------------------------------------
extern "C" void kernel_launch(void* const* d_in, const int* in_sizes, int n_in,
                              void* d_out, int out_size)
{
    const float* x  = (const float*)d_in[0];
    const float* W  = (const float*)d_in[1];
    const int*   rp = (const int*)d_in[2];
    float*       out = (float*)d_out;

    dim3 grid(LL / IPB, HH);
    irpe_fused2_kernel<<<grid, 256>>>(x, W, rp, out);
}

// round 6
// speedup vs baseline: 1.4553x; 1.0762x over previous
#include <cuda_runtime.h>
#include <cstdint>

// Problem constants:
//   B=8, H=8, L=1024, D=64, K=49
//   x:  (B,H,L,D) fp32   = d_in[0]
//   W:  (H,D,K)   fp32   = d_in[1]
//   rp: (L,L)     int32  = d_in[2]
//   out:(B,H,L,L) fp32
#define BB 8
#define HH 8
#define LL 1024
#define DD 64
#define KK 49
#define BH (BB*HH)

#define WS_STRIDE 50       // padded W row stride in smem (even -> aligned pairs)
#define IPB 8              // i-rows per block (one per warp)

// ---------------------------------------------------------------------------
// Fused kernel v3: register-resident lt + SHFL gather (no smem gather at all).
//
// Block (i-group, h): 8 warps; warp w owns i = i0+w and ALL 8 b's.
//   compute: lt[b][k] in registers, b-pairs packed in fma.rn.f32x2;
//            x broadcast via shfl from registers; W: 2 LDS per d per warp.
//            Layout after unpack: f0[b] = lt[b][lane], f1[b] = lt[b][lane+32]
//            (f1 valid in lanes 0..16, covering k=32..48).
//   gather:  out[bh,i,j] = lt[b][rp[i,j]] via two shfls + select per element.
//            rp read from global LDG.128, reused across 8 b in registers.
// grid: (L/8, H) = (128, 8), block: 256
// ---------------------------------------------------------------------------
__global__ __launch_bounds__(256, 4) void irpe_fused3_kernel(
    const float* __restrict__ x, const float* __restrict__ W,
    const int* __restrict__ rp, float* __restrict__ out)
{
    const int h    = blockIdx.y;
    const int i0   = blockIdx.x * IPB;
    const int tid  = threadIdx.x;
    const int w    = tid >> 5;
    const int lane = tid & 31;
    const int i    = i0 + w;

    __shared__ float Ws[DD * WS_STRIDE + 32];   // ~13 KB (pad: safe lane+32 reads)

    // Stage W[h] into stride-50 rows
    {
        const float* Wh = W + (size_t)h * DD * KK;
        #pragma unroll
        for (int t = tid; t < DD * KK; t += 256) {
            const int d = t / KK;
            const int k = t - d * KK;
            Ws[d * WS_STRIDE + k] = Wh[t];
        }
    }

    // Load x into registers: lane (b=lane>>2, q=lane&3) holds x[b*8+h, i, q*16..q*16+15]
    float xr[16];
    {
        const int b = lane >> 2;
        const int q = lane & 3;
        const float4* src = (const float4*)(x + ((size_t)(b * HH + h) * LL + i) * DD + q * 16);
        #pragma unroll
        for (int n = 0; n < 4; n++) {
            float4 v = src[n];
            xr[n * 4 + 0] = v.x; xr[n * 4 + 1] = v.y;
            xr[n * 4 + 2] = v.z; xr[n * 4 + 3] = v.w;
        }
    }
    __syncthreads();

    // Compute: acc[bp]   = { lt[2bp][lane],   lt[2bp+1][lane]   }  (packed f32x2)
    //          acc[4+bp] = { lt[2bp][lane+32], lt[2bp+1][lane+32] } (lanes 0..16)
    unsigned long long acc[8];
    #pragma unroll
    for (int j = 0; j < 8; j++) acc[j] = 0ull;

    for (int q = 0; q < 4; q++) {
        #pragma unroll
        for (int d2 = 0; d2 < 16; d2++) {
            const int d = q * 16 + d2;
            const float w0 = Ws[d * WS_STRIDE + lane];
            const float w1 = Ws[d * WS_STRIDE + 32 + lane];  // junk for lane>=17, discarded
            unsigned long long wp0, wp1;
            asm("mov.b64 %0, {%1, %1};" : "=l"(wp0) : "f"(w0));
            asm("mov.b64 %0, {%1, %1};" : "=l"(wp1) : "f"(w1));
            #pragma unroll
            for (int bp = 0; bp < 4; bp++) {
                const float x0 = __shfl_sync(0xffffffffu, xr[d2], bp * 8 + q);
                const float x1 = __shfl_sync(0xffffffffu, xr[d2], bp * 8 + 4 + q);
                unsigned long long xp;
                asm("mov.b64 %0, {%1, %2};" : "=l"(xp) : "f"(x0), "f"(x1));
                asm("fma.rn.f32x2 %0, %1, %2, %0;" : "+l"(acc[bp])     : "l"(xp), "l"(wp0));
                asm("fma.rn.f32x2 %0, %1, %2, %0;" : "+l"(acc[4 + bp]) : "l"(xp), "l"(wp1));
            }
        }
    }

    // Unpack to gather layout: f0[b] = lt[b][lane], f1[b] = lt[b][lane+32]
    float f0[BB], f1[BB];
    #pragma unroll
    for (int bp = 0; bp < 4; bp++) {
        asm("mov.b64 {%0, %1}, %2;" : "=f"(f0[2 * bp]), "=f"(f0[2 * bp + 1]) : "l"(acc[bp]));
        asm("mov.b64 {%0, %1}, %2;" : "=f"(f1[2 * bp]), "=f"(f1[2 * bp + 1]) : "l"(acc[4 + bp]));
    }

    // Gather via shfl + streaming stores. Warp-synchronous throughout.
    const int4* rrow = (const int4*)(rp + (size_t)i * LL);
    for (int it = 0; it < 8; it++) {
        const int4 bk = rrow[it * 32 + lane];      // coalesced LDG.128, used once
        #pragma unroll
        for (int b = 0; b < BB; b++) {
            float4 v;
            {
                float a0 = __shfl_sync(0xffffffffu, f0[b], bk.x);
                float a1 = __shfl_sync(0xffffffffu, f1[b], bk.x - 32);
                v.x = (bk.x < 32) ? a0 : a1;
            }
            {
                float a0 = __shfl_sync(0xffffffffu, f0[b], bk.y);
                float a1 = __shfl_sync(0xffffffffu, f1[b], bk.y - 32);
                v.y = (bk.y < 32) ? a0 : a1;
            }
            {
                float a0 = __shfl_sync(0xffffffffu, f0[b], bk.z);
                float a1 = __shfl_sync(0xffffffffu, f1[b], bk.z - 32);
                v.z = (bk.z < 32) ? a0 : a1;
            }
            {
                float a0 = __shfl_sync(0xffffffffu, f0[b], bk.w);
                float a1 = __shfl_sync(0xffffffffu, f1[b], bk.w - 32);
                v.w = (bk.w < 32) ? a0 : a1;
            }
            float4* dst = (float4*)(out + (((size_t)(b * HH + h)) * LL + i) * LL);
            __stcs(dst + it * 32 + lane, v);
        }
    }
}

// ---------------------------------------------------------------------------
extern "C" void kernel_launch(void* const* d_in, const int* in_sizes, int n_in,
                              void* d_out, int out_size)
{
    const float* x  = (const float*)d_in[0];
    const float* W  = (const float*)d_in[1];
    const int*   rp = (const int*)d_in[2];
    float*       out = (float*)d_out;

    dim3 grid(LL / IPB, HH);
    irpe_fused3_kernel<<<grid, 256>>>(x, W, rp, out);
}

// round 7
// speedup vs baseline: 1.5022x; 1.0322x over previous
#include <cuda_runtime.h>
#include <cstdint>

// Problem constants:
//   B=8, H=8, L=1024, D=64, K=49
//   x:  (B,H,L,D) fp32   = d_in[0]
//   W:  (H,D,K)   fp32   = d_in[1]
//   rp: (L,L)     int32  = d_in[2]
//   out:(B,H,L,L) fp32
#define BB 8
#define HH 8
#define LL 1024
#define DD 64
#define KK 49
#define BH (BB*HH)

#define WS_STRIDE 50       // padded W row stride in smem (even -> aligned pairs)
#define IPB 8              // i-rows per block (one per warp)

// ---------------------------------------------------------------------------
// Fused kernel v4: register-resident lt + SHFL gather; x staged TRANSPOSED in
// smem so the FFMA2 multiplier pair {x[2bp],x[2bp+1]} is one broadcast LDS.64
// (replaces 2 SHFL + 1 MOV per bp per d of v3).
//
// Block (i-group, h): 8 warps; warp w owns i = i0+w and ALL 8 b's.
//   compute: acc[bp]   = { lt[2bp][lane],   lt[2bp+1][lane]   }
//            acc[4+bp] = { lt[2bp][lane+32], lt[2bp+1][lane+32] } (lanes 0..16)
//   gather:  out[bh,i,j] = lt[b][rp[i,j]] via shfl(f0,bk)/shfl(f1,bk) + select
//            (shfl wraps idx mod 32, so no bk-32 needed).
// grid: (L/8, H) = (128, 8), block: 256
// ---------------------------------------------------------------------------
__global__ __launch_bounds__(256, 5) void irpe_fused4_kernel(
    const float* __restrict__ x, const float* __restrict__ W,
    const int* __restrict__ rp, float* __restrict__ out)
{
    const int h    = blockIdx.y;
    const int i0   = blockIdx.x * IPB;
    const int tid  = threadIdx.x;
    const int w    = tid >> 5;
    const int lane = tid & 31;
    const int i    = i0 + w;

    __shared__ float Ws[DD * WS_STRIDE + 32];     // ~12.9 KB
    __shared__ float xst[IPB * DD * BB];          // [w][d][b], 16 KB

    // Stage W[h] into stride-50 rows
    {
        const float* Wh = W + (size_t)h * DD * KK;
        #pragma unroll
        for (int t = tid; t < DD * KK; t += 256) {
            const int d = t / KK;
            const int k = t - d * KK;
            Ws[d * WS_STRIDE + k] = Wh[t];
        }
    }

    // Stage x transposed: xst[w][d][b] = x[b*8+h][i0+w][d]
    // 1024 float4 loads spread over 256 threads (4 each).
    #pragma unroll
    for (int t = tid; t < IPB * BB * (DD / 4); t += 256) {
        const int ww = t >> 7;            // warp/i slot
        const int rem = t & 127;
        const int b  = rem >> 4;
        const int q  = rem & 15;          // quad along d
        float4 v = *(const float4*)(x + ((size_t)(b * HH + h) * LL + i0 + ww) * DD + q * 4);
        float* dst = xst + (ww * DD + q * 4) * BB + b;
        dst[0 * BB] = v.x;
        dst[1 * BB] = v.y;
        dst[2 * BB] = v.z;
        dst[3 * BB] = v.w;
    }
    __syncthreads();

    // Compute
    unsigned long long acc[8];
    #pragma unroll
    for (int j = 0; j < 8; j++) acc[j] = 0ull;

    const unsigned long long* xw = (const unsigned long long*)(xst + w * DD * BB);

    #pragma unroll 16
    for (int d = 0; d < DD; d++) {
        const float w0 = Ws[d * WS_STRIDE + lane];
        const float w1 = Ws[d * WS_STRIDE + 32 + lane];  // junk lanes>=17, discarded
        unsigned long long wp0, wp1;
        asm("mov.b64 %0, {%1, %1};" : "=l"(wp0) : "f"(w0));
        asm("mov.b64 %0, {%1, %1};" : "=l"(wp1) : "f"(w1));
        #pragma unroll
        for (int bp = 0; bp < 4; bp++) {
            const unsigned long long xp = xw[d * (BB / 2) + bp];   // broadcast LDS.64
            asm("fma.rn.f32x2 %0, %1, %2, %0;" : "+l"(acc[bp])     : "l"(xp), "l"(wp0));
            asm("fma.rn.f32x2 %0, %1, %2, %0;" : "+l"(acc[4 + bp]) : "l"(xp), "l"(wp1));
        }
    }

    // Unpack to gather layout: f0[b] = lt[b][lane], f1[b] = lt[b][lane+32]
    float f0[BB], f1[BB];
    #pragma unroll
    for (int bp = 0; bp < 4; bp++) {
        asm("mov.b64 {%0, %1}, %2;" : "=f"(f0[2 * bp]), "=f"(f0[2 * bp + 1]) : "l"(acc[bp]));
        asm("mov.b64 {%0, %1}, %2;" : "=f"(f1[2 * bp]), "=f"(f1[2 * bp + 1]) : "l"(acc[4 + bp]));
    }

    // Gather via shfl + streaming stores (shfl wraps idx mod 32).
    const int4* rrow = (const int4*)(rp + (size_t)i * LL);
    for (int it = 0; it < 8; it++) {
        const int4 bk = rrow[it * 32 + lane];      // coalesced LDG.128, used once
        #pragma unroll
        for (int b = 0; b < BB; b++) {
            float4 v;
            {
                float a0 = __shfl_sync(0xffffffffu, f0[b], bk.x);
                float a1 = __shfl_sync(0xffffffffu, f1[b], bk.x);
                v.x = (bk.x < 32) ? a0 : a1;
            }
            {
                float a0 = __shfl_sync(0xffffffffu, f0[b], bk.y);
                float a1 = __shfl_sync(0xffffffffu, f1[b], bk.y);
                v.y = (bk.y < 32) ? a0 : a1;
            }
            {
                float a0 = __shfl_sync(0xffffffffu, f0[b], bk.z);
                float a1 = __shfl_sync(0xffffffffu, f1[b], bk.z);
                v.z = (bk.z < 32) ? a0 : a1;
            }
            {
                float a0 = __shfl_sync(0xffffffffu, f0[b], bk.w);
                float a1 = __shfl_sync(0xffffffffu, f1[b], bk.w);
                v.w = (bk.w < 32) ? a0 : a1;
            }
            float4* dst = (float4*)(out + (((size_t)(b * HH + h)) * LL + i) * LL);
            __stcs(dst + it * 32 + lane, v);
        }
    }
}

// ---------------------------------------------------------------------------
extern "C" void kernel_launch(void* const* d_in, const int* in_sizes, int n_in,
                              void* d_out, int out_size)
{
    const float* x  = (const float*)d_in[0];
    const float* W  = (const float*)d_in[1];
    const int*   rp = (const int*)d_in[2];
    float*       out = (float*)d_out;

    dim3 grid(LL / IPB, HH);
    irpe_fused4_kernel<<<grid, 256>>>(x, W, rp, out);
}